// round 1
// baseline (speedup 1.0000x reference)
#include <cuda_runtime.h>
#include <math.h>

#define B_ 4
#define L_ 1024
#define D_ 1024
#define H_ 16
#define HD_ 64
#define D3_ 3072
#define ADJW (L_/32)

// Scratch (device globals: allocation-free rule)
__device__ float g_qkv[B_*L_*D3_];            // 48 MB   [B,L,3D]
__device__ float g_scores[B_*H_*L_*L_];       // 256 MB  [B,H,L,L]
__device__ float g_attn[B_*L_*D_];            // 16 MB   [B,L,D]
__device__ unsigned g_adj[L_*ADJW];           // 128 KB  bitmask

// ---------------------------------------------------------------------------
// Adjacency build
// ---------------------------------------------------------------------------
__global__ void zero_adj_kernel(unsigned* adj) {
    int i = blockIdx.x * blockDim.x + threadIdx.x;
    if (i < L_*ADJW) adj[i] = 0u;
}

__global__ void build_adj_kernel(unsigned* adj, const int* __restrict__ edges, int E) {
    int e = blockIdx.x * blockDim.x + threadIdx.x;
    if (e < E) {
        int i = edges[2*e], j = edges[2*e+1];
        atomicOr(&adj[i*ADJW + (j >> 5)], 1u << (j & 31));
        atomicOr(&adj[j*ADJW + (i >> 5)], 1u << (i & 31));
    }
}

// ---------------------------------------------------------------------------
// Generic tiled SIMT fp32 GEMM.
//   BT=true : C[m,n] = alpha * sum_k A[m*lda+k] * B[n*ldb+k]  (+bias[n])
//   BT=false: C[m,n] = alpha * sum_k A[m*lda+k] * B[k*ldb+n]  (+bias[n])
// Batched via blockIdx.z with two-level (outer,inner) offsets so we can
// address per-(batch,head) slices of the packed qkv buffer.
// All problem sizes divide the tiles exactly -> no bounds checks.
// ---------------------------------------------------------------------------
template<int BM, int BN, int BK, int TM, int TN, bool BT>
__global__ void __launch_bounds__(256)
gemm_kernel(const float* __restrict__ A, const float* __restrict__ B,
            const float* __restrict__ bias, float* __restrict__ C,
            int lda, int ldb, int ldc, int K,
            int batch_inner,
            long sAo, long sAi, long sBo, long sBi, long sCo, long sCi,
            float alpha)
{
    constexpr int TX = BN / TN;
    constexpr int TY = BM / TM;
    static_assert(TX * TY == 256, "thread grid must be 256");

    __shared__ float As[BK][BM + 4];
    __shared__ float Bs[BK][BN + 4];

    const int z  = blockIdx.z;
    const int zo = z / batch_inner;
    const int zi = z - zo * batch_inner;
    A += zo * sAo + zi * sAi;
    B += zo * sBo + zi * sBi;
    C += zo * sCo + zi * sCi;

    const int tid = threadIdx.x;
    const int tx  = tid % TX;
    const int ty  = tid / TX;
    const int m0  = blockIdx.y * BM;
    const int n0  = blockIdx.x * BN;

    float acc[TM][TN];
    #pragma unroll
    for (int i = 0; i < TM; i++)
        #pragma unroll
        for (int j = 0; j < TN; j++) acc[i][j] = 0.0f;

    for (int k0 = 0; k0 < K; k0 += BK) {
        // ---- A tile: BM x BK, K-contiguous, transpose into As[k][m]
        {
            constexpr int RPP = 256 / (BK / 4);     // rows per pass (64 for BK=16)
            #pragma unroll
            for (int p = 0; p < BM / RPP; p++) {
                int r  = tid / (BK / 4) + p * RPP;
                int c4 = (tid % (BK / 4)) * 4;
                const float4 v = *(const float4*)(A + (long)(m0 + r) * lda + k0 + c4);
                As[c4+0][r] = v.x; As[c4+1][r] = v.y;
                As[c4+2][r] = v.z; As[c4+3][r] = v.w;
            }
        }
        // ---- B tile
        if (BT) {   // B[n][k] (K-contiguous), transpose into Bs[k][n]
            constexpr int RPP = 256 / (BK / 4);
            #pragma unroll
            for (int p = 0; p < BN / RPP; p++) {
                int r  = tid / (BK / 4) + p * RPP;
                int c4 = (tid % (BK / 4)) * 4;
                const float4 v = *(const float4*)(B + (long)(n0 + r) * ldb + k0 + c4);
                Bs[c4+0][r] = v.x; Bs[c4+1][r] = v.y;
                Bs[c4+2][r] = v.z; Bs[c4+3][r] = v.w;
            }
        } else {    // B[k][n] (N-contiguous), direct copy Bs[k][n]
            constexpr int CPP = BN / 4;             // float4 per row
            constexpr int RPP = 256 / CPP;
            #pragma unroll
            for (int p = 0; p < BK / RPP; p++) {
                int r  = tid / CPP + p * RPP;
                int c4 = (tid % CPP) * 4;
                *(float4*)&Bs[r][c4] = *(const float4*)(B + (long)(k0 + r) * ldb + n0 + c4);
            }
        }
        __syncthreads();

        #pragma unroll
        for (int kk = 0; kk < BK; kk++) {
            float a[TM], b[TN];
            #pragma unroll
            for (int i = 0; i < TM; i += 4)
                *(float4*)&a[i] = *(const float4*)&As[kk][ty*TM + i];
            #pragma unroll
            for (int j = 0; j < TN; j += 4)
                *(float4*)&b[j] = *(const float4*)&Bs[kk][tx*TN + j];
            #pragma unroll
            for (int i = 0; i < TM; i++)
                #pragma unroll
                for (int j = 0; j < TN; j++)
                    acc[i][j] = fmaf(a[i], b[j], acc[i][j]);
        }
        __syncthreads();
    }

    #pragma unroll
    for (int i = 0; i < TM; i++) {
        long m = m0 + ty*TM + i;
        #pragma unroll
        for (int j = 0; j < TN; j += 4) {
            int n = n0 + tx*TN + j;
            float4 v;
            v.x = acc[i][j+0] * alpha;
            v.y = acc[i][j+1] * alpha;
            v.z = acc[i][j+2] * alpha;
            v.w = acc[i][j+3] * alpha;
            if (bias) {
                v.x += bias[n+0]; v.y += bias[n+1];
                v.z += bias[n+2]; v.w += bias[n+3];
            }
            *(float4*)(C + m * (long)ldc + n) = v;
        }
    }
}

// ---------------------------------------------------------------------------
// Mask + softmax over one score row (L=1024), 256 threads x 4 elems (float4).
// ---------------------------------------------------------------------------
__global__ void softmax_kernel(float* __restrict__ scores, const unsigned* __restrict__ adj)
{
    __shared__ float red_max[8];
    __shared__ float red_sum[8];

    const long row = blockIdx.x;                // (b*H+h)*L + q
    const int  q   = (int)(row & (L_ - 1));
    float* s = scores + row * L_;
    const int tid = threadIdx.x;

    float4 v = *(float4*)(s + tid * 4);
    const unsigned w  = adj[q * ADJW + (tid >> 3)];
    const unsigned sh = (tid * 4) & 31;
    if ((w >> (sh+0)) & 1u) v.x = -INFINITY;
    if ((w >> (sh+1)) & 1u) v.y = -INFINITY;
    if ((w >> (sh+2)) & 1u) v.z = -INFINITY;
    if ((w >> (sh+3)) & 1u) v.w = -INFINITY;

    float mx = fmaxf(fmaxf(v.x, v.y), fmaxf(v.z, v.w));
    #pragma unroll
    for (int o = 16; o > 0; o >>= 1) mx = fmaxf(mx, __shfl_xor_sync(0xFFFFFFFFu, mx, o));
    if ((tid & 31) == 0) red_max[tid >> 5] = mx;
    __syncthreads();
    float bm = red_max[0];
    #pragma unroll
    for (int i = 1; i < 8; i++) bm = fmaxf(bm, red_max[i]);

    float e0 = __expf(v.x - bm), e1 = __expf(v.y - bm);
    float e2 = __expf(v.z - bm), e3 = __expf(v.w - bm);
    float sm = e0 + e1 + e2 + e3;
    #pragma unroll
    for (int o = 16; o > 0; o >>= 1) sm += __shfl_xor_sync(0xFFFFFFFFu, sm, o);
    if ((tid & 31) == 0) red_sum[tid >> 5] = sm;
    __syncthreads();
    float bs = 0.0f;
    #pragma unroll
    for (int i = 0; i < 8; i++) bs += red_sum[i];

    const float inv = 1.0f / bs;
    *(float4*)(s + tid * 4) = make_float4(e0*inv, e1*inv, e2*inv, e3*inv);
}

// ---------------------------------------------------------------------------
// Launch
// ---------------------------------------------------------------------------
extern "C" void kernel_launch(void* const* d_in, const int* in_sizes, int n_in,
                              void* d_out, int out_size)
{
    const float* x     = (const float*)d_in[0];
    const int*   edges = (const int*)  d_in[1];
    const float* w_qkv = (const float*)d_in[2];
    const float* b_qkv = (const float*)d_in[3];
    const float* w_out = (const float*)d_in[4];
    const float* b_out = (const float*)d_in[5];
    float* out = (float*)d_out;
    const int E = in_sizes[1] / 2;

    float *qkv, *scores, *attn; unsigned* adj;
    cudaGetSymbolAddress((void**)&qkv,    g_qkv);
    cudaGetSymbolAddress((void**)&scores, g_scores);
    cudaGetSymbolAddress((void**)&attn,   g_attn);
    cudaGetSymbolAddress((void**)&adj,    g_adj);

    // 1) adjacency bitmask
    zero_adj_kernel<<<(L_*ADJW + 255) / 256, 256>>>(adj);
    build_adj_kernel<<<(E + 255) / 256, 256>>>(adj, edges, E);

    // 2) QKV projection: [4096,3072] = X[4096,1024] @ Wqkv[3072,1024]^T + b
    {
        dim3 g(D3_/128, (B_*L_)/128, 1);
        gemm_kernel<128,128,16,8,8,true><<<g, 256>>>(
            x, w_qkv, b_qkv, qkv,
            D_, D_, D3_, D_,
            1, 0,0, 0,0, 0,0, 1.0f);
    }

    // 3) scores[b,h] = (Q_h * 1/8) @ K_h^T   (M=N=1024, K=64, 64 batches)
    {
        dim3 g(L_/128, L_/128, B_*H_);
        gemm_kernel<128,128,16,8,8,true><<<g, 256>>>(
            qkv, qkv + D_, nullptr, scores,
            D3_, D3_, L_, HD_,
            H_,
            (long)L_*D3_, (long)HD_,        // A: per-b, per-h
            (long)L_*D3_, (long)HD_,        // B: per-b, per-h
            (long)H_*L_*L_, (long)L_*L_,    // C: per-b, per-h
            0.125f);
    }

    // 4) mask + softmax (in place on scores)
    softmax_kernel<<<B_*H_*L_, 256>>>(scores, adj);

    // 5) attn_out[b,:,h*64:+64] = P[b,h] @ V_h   (M=1024, N=64, K=1024)
    {
        dim3 g(HD_/64, L_/128, B_*H_);
        gemm_kernel<128,64,16,8,4,false><<<g, 256>>>(
            scores, qkv + 2*D_, nullptr, attn,
            L_, D3_, D_, L_,
            H_,
            (long)H_*L_*L_, (long)L_*L_,    // A = P
            (long)L_*D3_,   (long)HD_,      // B = V
            (long)L_*D_,    (long)HD_,      // C = attn_out
            1.0f);
    }

    // 6) out projection: [4096,1024] = attn[4096,1024] @ Wout[1024,1024]^T + b
    {
        dim3 g(D_/128, (B_*L_)/128, 1);
        gemm_kernel<128,128,16,8,8,true><<<g, 256>>>(
            attn, w_out, b_out, out,
            D_, D_, D_, D_,
            1, 0,0, 0,0, 0,0, 1.0f);
    }
}

// round 4
// speedup vs baseline: 1.8505x; 1.8505x over previous
#include <cuda_runtime.h>
#include <math.h>
#include <stdint.h>

#define B_ 4
#define L_ 1024
#define D_ 1024
#define H_ 16
#define HD_ 64
#define D3_ 3072
#define ADJW (L_/32)

// Scratch (device globals: allocation-free rule)
__device__ float g_qkv[B_*L_*D3_];            // 48 MB   [B,L,3D]
__device__ float g_scores[B_*H_*L_*L_];       // 256 MB  [B,H,L,L]
__device__ float g_attn[B_*L_*D_];            // 16 MB   [B,L,D]
__device__ unsigned g_adj[L_*ADJW];           // 128 KB  bitmask

// ---------------------------------------------------------------------------
// Helpers
// ---------------------------------------------------------------------------
__device__ __forceinline__ uint32_t f2tf32(float x) {
    uint32_t r;
    asm("cvt.rna.tf32.f32 %0, %1;" : "=r"(r) : "f"(x));
    return r;
}

__device__ __forceinline__ void mma_tf32(float* d, const uint32_t* a, const uint32_t* b) {
    asm volatile(
        "mma.sync.aligned.m16n8k8.row.col.f32.tf32.tf32.f32 "
        "{%0,%1,%2,%3}, {%4,%5,%6,%7}, {%8,%9}, {%0,%1,%2,%3};"
        : "+f"(d[0]), "+f"(d[1]), "+f"(d[2]), "+f"(d[3])
        : "r"(a[0]), "r"(a[1]), "r"(a[2]), "r"(a[3]),
          "r"(b[0]), "r"(b[1]));
}

// ---------------------------------------------------------------------------
// Adjacency build
// ---------------------------------------------------------------------------
__global__ void zero_adj_kernel(unsigned* adj) {
    int i = blockIdx.x * blockDim.x + threadIdx.x;
    if (i < L_*ADJW) adj[i] = 0u;
}

__global__ void build_adj_kernel(unsigned* adj, const int* __restrict__ edges, int E) {
    int e = blockIdx.x * blockDim.x + threadIdx.x;
    if (e < E) {
        int i = edges[2*e], j = edges[2*e+1];
        atomicOr(&adj[i*ADJW + (j >> 5)], 1u << (j & 31));
        atomicOr(&adj[j*ADJW + (i >> 5)], 1u << (i & 31));
    }
}

// ---------------------------------------------------------------------------
// Tensor-core tf32 GEMM.
//   BT=true : C[m,n] = alpha * sum_k A[m*lda+k] * B[n*ldb+k]  (+bias[n])
//   BT=false: C[m,n] = alpha * sum_k A[m*lda+k] * B[k*ldb+n]  (+bias[n])
// Warp tile 64x32 (MI=4 m16-tiles x NI=4 n8-tiles), m16n8k8 tf32 MMA.
// Smem PAD=8 makes fragment LDS bank-conflict-free (stride ≡ 8 mod 32).
// All sizes divide tiles exactly -> no bounds checks.
// ---------------------------------------------------------------------------
template<int BM, int BN, int BK, int WM, int WN, bool BT>
__global__ void __launch_bounds__(WM*WN*32)
gemm_tc(const float* __restrict__ A, const float* __restrict__ Bm,
        const float* __restrict__ bias, float* __restrict__ C,
        int lda, int ldb, int ldc, int K,
        int batch_inner,
        long sAo, long sAi, long sBo, long sBi, long sCo, long sCi,
        float alpha)
{
    constexpr int NT  = WM*WN*32;
    constexpr int WTM = BM/WM;      // 64
    constexpr int WTN = BN/WN;      // 32
    constexpr int MI  = WTM/16;     // 4
    constexpr int NI  = WTN/8;      // 4
    constexpr int PAD = 8;
    static_assert(WTM % 16 == 0 && WTN % 8 == 0, "warp tile");
    static_assert(BK % 8 == 0, "BK");

    __shared__ uint32_t As[BK][BM+PAD];
    __shared__ uint32_t Bs[BK][BN+PAD];

    const int z  = blockIdx.z;
    const int zo = z / batch_inner;
    const int zi = z - zo * batch_inner;
    A  += zo * sAo + zi * sAi;
    Bm += zo * sBo + zi * sBi;
    C  += zo * sCo + zi * sCi;

    const int tid  = threadIdx.x;
    const int wid  = tid >> 5;
    const int lane = tid & 31;
    const int wm   = wid / WN;
    const int wn   = wid % WN;
    const int m0   = blockIdx.y * BM;
    const int n0   = blockIdx.x * BN;
    const int lr   = lane >> 2;     // 0..7
    const int lc   = lane & 3;      // 0..3

    float acc[MI][NI][4];
    #pragma unroll
    for (int i = 0; i < MI; i++)
        #pragma unroll
        for (int j = 0; j < NI; j++)
            #pragma unroll
            for (int r = 0; r < 4; r++) acc[i][j][r] = 0.0f;

    for (int k0 = 0; k0 < K; k0 += BK) {
        // ---- A tile: BM x BK, K-contiguous -> As[k][m] (transposed)
        {
            constexpr int CP  = BK/4;
            constexpr int RPP = NT / CP;
            #pragma unroll
            for (int p = 0; p < BM/RPP; p++) {
                int r  = tid / CP + p * RPP;
                int c4 = (tid % CP) * 4;
                const float4 v = *(const float4*)(A + (long)(m0 + r) * lda + k0 + c4);
                As[c4+0][r] = f2tf32(v.x); As[c4+1][r] = f2tf32(v.y);
                As[c4+2][r] = f2tf32(v.z); As[c4+3][r] = f2tf32(v.w);
            }
        }
        // ---- B tile -> Bs[k][n]
        if (BT) {   // B[n][k] K-contiguous, transpose
            constexpr int CP  = BK/4;
            constexpr int RPP = NT / CP;
            #pragma unroll
            for (int p = 0; p < BN/RPP; p++) {
                int r  = tid / CP + p * RPP;
                int c4 = (tid % CP) * 4;
                const float4 v = *(const float4*)(Bm + (long)(n0 + r) * ldb + k0 + c4);
                Bs[c4+0][r] = f2tf32(v.x); Bs[c4+1][r] = f2tf32(v.y);
                Bs[c4+2][r] = f2tf32(v.z); Bs[c4+3][r] = f2tf32(v.w);
            }
        } else {    // B[k][n] N-contiguous, direct
            constexpr int CP  = BN/4;
            constexpr int RPP = NT / CP;
            #pragma unroll
            for (int p = 0; p < BK/RPP; p++) {
                int r  = tid / CP + p * RPP;
                int c4 = (tid % CP) * 4;
                const float4 v = *(const float4*)(Bm + (long)(k0 + r) * ldb + n0 + c4);
                Bs[r][c4+0] = f2tf32(v.x); Bs[r][c4+1] = f2tf32(v.y);
                Bs[r][c4+2] = f2tf32(v.z); Bs[r][c4+3] = f2tf32(v.w);
            }
        }
        __syncthreads();

        #pragma unroll
        for (int kk = 0; kk < BK; kk += 8) {
            uint32_t af[MI][4], bf[NI][2];
            #pragma unroll
            for (int i = 0; i < MI; i++) {
                int mm = wm*WTM + i*16;
                af[i][0] = As[kk+lc  ][mm+lr  ];
                af[i][1] = As[kk+lc  ][mm+lr+8];
                af[i][2] = As[kk+lc+4][mm+lr  ];
                af[i][3] = As[kk+lc+4][mm+lr+8];
            }
            #pragma unroll
            for (int j = 0; j < NI; j++) {
                int nn = wn*WTN + j*8;
                bf[j][0] = Bs[kk+lc  ][nn+lr];
                bf[j][1] = Bs[kk+lc+4][nn+lr];
            }
            #pragma unroll
            for (int i = 0; i < MI; i++)
                #pragma unroll
                for (int j = 0; j < NI; j++)
                    mma_tf32(acc[i][j], af[i], bf[j]);
        }
        __syncthreads();
    }

    // ---- epilogue: c0,c1 at (lr, lc*2), c2,c3 at (lr+8, lc*2)
    #pragma unroll
    for (int i = 0; i < MI; i++) {
        #pragma unroll
        for (int j = 0; j < NI; j++) {
            const int  mm = m0 + wm*WTM + i*16 + lr;
            const int  nn = n0 + wn*WTN + j*8 + lc*2;
            float2 v0 = make_float2(acc[i][j][0]*alpha, acc[i][j][1]*alpha);
            float2 v1 = make_float2(acc[i][j][2]*alpha, acc[i][j][3]*alpha);
            if (bias) {
                const float2 bb = *(const float2*)(bias + nn);
                v0.x += bb.x; v0.y += bb.y;
                v1.x += bb.x; v1.y += bb.y;
            }
            *(float2*)(C + (long)mm * ldc + nn)     = v0;
            *(float2*)(C + (long)(mm+8) * ldc + nn) = v1;
        }
    }
}

// ---------------------------------------------------------------------------
// Mask + softmax over one score row (L=1024), 256 threads x 4 elems.
// ---------------------------------------------------------------------------
__global__ void softmax_kernel(float* __restrict__ scores, const unsigned* __restrict__ adj)
{
    __shared__ float red_max[8];
    __shared__ float red_sum[8];

    const long row = blockIdx.x;                // (b*H+h)*L + q
    const int  q   = (int)(row & (L_ - 1));
    float* s = scores + row * L_;
    const int tid = threadIdx.x;

    float4 v = *(float4*)(s + tid * 4);
    const unsigned w  = adj[q * ADJW + (tid >> 3)];
    const unsigned sh = (tid * 4) & 31;
    if ((w >> (sh+0)) & 1u) v.x = -INFINITY;
    if ((w >> (sh+1)) & 1u) v.y = -INFINITY;
    if ((w >> (sh+2)) & 1u) v.z = -INFINITY;
    if ((w >> (sh+3)) & 1u) v.w = -INFINITY;

    float mx = fmaxf(fmaxf(v.x, v.y), fmaxf(v.z, v.w));
    #pragma unroll
    for (int o = 16; o > 0; o >>= 1) mx = fmaxf(mx, __shfl_xor_sync(0xFFFFFFFFu, mx, o));
    if ((tid & 31) == 0) red_max[tid >> 5] = mx;
    __syncthreads();
    float bm = red_max[0];
    #pragma unroll
    for (int i = 1; i < 8; i++) bm = fmaxf(bm, red_max[i]);

    float e0 = __expf(v.x - bm), e1 = __expf(v.y - bm);
    float e2 = __expf(v.z - bm), e3 = __expf(v.w - bm);
    float sm = e0 + e1 + e2 + e3;
    #pragma unroll
    for (int o = 16; o > 0; o >>= 1) sm += __shfl_xor_sync(0xFFFFFFFFu, sm, o);
    if ((tid & 31) == 0) red_sum[tid >> 5] = sm;
    __syncthreads();
    float bs = 0.0f;
    #pragma unroll
    for (int i = 0; i < 8; i++) bs += red_sum[i];

    const float inv = 1.0f / bs;
    *(float4*)(s + tid * 4) = make_float4(e0*inv, e1*inv, e2*inv, e3*inv);
}

// ---------------------------------------------------------------------------
// Launch
// ---------------------------------------------------------------------------
extern "C" void kernel_launch(void* const* d_in, const int* in_sizes, int n_in,
                              void* d_out, int out_size)
{
    const float* x     = (const float*)d_in[0];
    const int*   edges = (const int*)  d_in[1];
    const float* w_qkv = (const float*)d_in[2];
    const float* b_qkv = (const float*)d_in[3];
    const float* w_out = (const float*)d_in[4];
    const float* b_out = (const float*)d_in[5];
    float* out = (float*)d_out;
    const int E = in_sizes[1] / 2;

    float *qkv, *scores, *attn; unsigned* adj;
    cudaGetSymbolAddress((void**)&qkv,    g_qkv);
    cudaGetSymbolAddress((void**)&scores, g_scores);
    cudaGetSymbolAddress((void**)&attn,   g_attn);
    cudaGetSymbolAddress((void**)&adj,    g_adj);

    // 1) adjacency bitmask
    zero_adj_kernel<<<(L_*ADJW + 255) / 256, 256>>>(adj);
    build_adj_kernel<<<(E + 255) / 256, 256>>>(adj, edges, E);

    // 2) QKV projection: [4096,3072] = X[4096,1024] @ Wqkv[3072,1024]^T + b
    {
        dim3 g(D3_/128, (B_*L_)/128, 1);
        gemm_tc<128,128,16,2,4,true><<<g, 256>>>(
            x, w_qkv, b_qkv, qkv,
            D_, D_, D3_, D_,
            1, 0,0, 0,0, 0,0, 1.0f);
    }

    // 3) scores[b,h] = (Q_h * 1/8) @ K_h^T   (M=N=1024, K=64, 64 batches)
    {
        dim3 g(L_/128, L_/128, B_*H_);
        gemm_tc<128,128,16,2,4,true><<<g, 256>>>(
            qkv, qkv + D_, nullptr, scores,
            D3_, D3_, L_, HD_,
            H_,
            (long)L_*D3_, (long)HD_,        // A: per-b, per-h
            (long)L_*D3_, (long)HD_,        // B: per-b, per-h
            (long)H_*L_*L_, (long)L_*L_,    // C: per-b, per-h
            0.125f);
    }

    // 4) mask + softmax (in place on scores)
    softmax_kernel<<<B_*H_*L_, 256>>>(scores, adj);

    // 5) attn_out[b,:,h*64:+64] = P[b,h] @ V_h   (M=1024, N=64, K=1024)
    {
        dim3 g(1, L_/128, B_*H_);
        gemm_tc<128,64,16,2,2,false><<<g, 128>>>(
            scores, qkv + 2*D_, nullptr, attn,
            L_, D3_, D_, L_,
            H_,
            (long)H_*L_*L_, (long)L_*L_,    // A = P
            (long)L_*D3_,   (long)HD_,      // B = V
            (long)L_*D_,    (long)HD_,      // C = attn_out
            1.0f);
    }

    // 6) out projection: [4096,1024] = attn[4096,1024] @ Wout[1024,1024]^T + b
    {
        dim3 g(D_/128, (B_*L_)/128, 1);
        gemm_tc<128,128,16,2,4,true><<<g, 256>>>(
            attn, w_out, b_out, out,
            D_, D_, D_, D_,
            1, 0,0, 0,0, 0,0, 1.0f);
    }
}

// round 6
// speedup vs baseline: 2.2830x; 1.2337x over previous
#include <cuda_runtime.h>
#include <math.h>
#include <stdint.h>

#define B_ 4
#define L_ 1024
#define D_ 1024
#define H_ 16
#define HD_ 64
#define D3_ 3072
#define ADJW (L_/32)

// Scratch (device globals: allocation-free rule)
__device__ float g_qkv[B_*L_*D3_];            // 48 MB   [B,L,3D]
__device__ float g_attn[B_*L_*D_];            // 16 MB   [B,L,D]
__device__ unsigned g_adj[L_*ADJW];           // 128 KB  bitmask

// ---------------------------------------------------------------------------
// Helpers
// ---------------------------------------------------------------------------
__device__ __forceinline__ uint32_t f2tf32(float x) {
    uint32_t r;
    asm("cvt.rna.tf32.f32 %0, %1;" : "=r"(r) : "f"(x));
    return r;
}

__device__ __forceinline__ void mma_tf32(float* d, const uint32_t* a, const uint32_t* b) {
    asm volatile(
        "mma.sync.aligned.m16n8k8.row.col.f32.tf32.tf32.f32 "
        "{%0,%1,%2,%3}, {%4,%5,%6,%7}, {%8,%9}, {%0,%1,%2,%3};"
        : "+f"(d[0]), "+f"(d[1]), "+f"(d[2]), "+f"(d[3])
        : "r"(a[0]), "r"(a[1]), "r"(a[2]), "r"(a[3]),
          "r"(b[0]), "r"(b[1]));
}

// ---------------------------------------------------------------------------
// Adjacency build
// ---------------------------------------------------------------------------
__global__ void zero_adj_kernel(unsigned* adj) {
    int i = blockIdx.x * blockDim.x + threadIdx.x;
    if (i < L_*ADJW) adj[i] = 0u;
}

__global__ void build_adj_kernel(unsigned* adj, const int* __restrict__ edges, int E) {
    int e = blockIdx.x * blockDim.x + threadIdx.x;
    if (e < E) {
        int i = edges[2*e], j = edges[2*e+1];
        atomicOr(&adj[i*ADJW + (j >> 5)], 1u << (j & 31));
        atomicOr(&adj[j*ADJW + (i >> 5)], 1u << (i & 31));
    }
}

// ---------------------------------------------------------------------------
// Tensor-core tf32 GEMM (projections).
//   BT=true : C[m,n] = alpha * sum_k A[m*lda+k] * B[n*ldb+k]  (+bias[n])
// ---------------------------------------------------------------------------
template<int BM, int BN, int BK, int WM, int WN, bool BT>
__global__ void __launch_bounds__(WM*WN*32)
gemm_tc(const float* __restrict__ A, const float* __restrict__ Bm,
        const float* __restrict__ bias, float* __restrict__ C,
        int lda, int ldb, int ldc, int K,
        int batch_inner,
        long sAo, long sAi, long sBo, long sBi, long sCo, long sCi,
        float alpha)
{
    constexpr int NT  = WM*WN*32;
    constexpr int WTM = BM/WM;
    constexpr int WTN = BN/WN;
    constexpr int MI  = WTM/16;
    constexpr int NI  = WTN/8;
    constexpr int PAD = 8;
    static_assert(WTM % 16 == 0 && WTN % 8 == 0, "warp tile");
    static_assert(BK % 8 == 0, "BK");

    __shared__ uint32_t As[BK][BM+PAD];
    __shared__ uint32_t Bs[BK][BN+PAD];

    const int z  = blockIdx.z;
    const int zo = z / batch_inner;
    const int zi = z - zo * batch_inner;
    A  += zo * sAo + zi * sAi;
    Bm += zo * sBo + zi * sBi;
    C  += zo * sCo + zi * sCi;

    const int tid  = threadIdx.x;
    const int wid  = tid >> 5;
    const int lane = tid & 31;
    const int wm   = wid / WN;
    const int wn   = wid % WN;
    const int m0   = blockIdx.y * BM;
    const int n0   = blockIdx.x * BN;
    const int lr   = lane >> 2;
    const int lc   = lane & 3;

    float acc[MI][NI][4];
    #pragma unroll
    for (int i = 0; i < MI; i++)
        #pragma unroll
        for (int j = 0; j < NI; j++)
            #pragma unroll
            for (int r = 0; r < 4; r++) acc[i][j][r] = 0.0f;

    for (int k0 = 0; k0 < K; k0 += BK) {
        {
            constexpr int CP  = BK/4;
            constexpr int RPP = NT / CP;
            #pragma unroll
            for (int p = 0; p < BM/RPP; p++) {
                int r  = tid / CP + p * RPP;
                int c4 = (tid % CP) * 4;
                const float4 v = *(const float4*)(A + (long)(m0 + r) * lda + k0 + c4);
                As[c4+0][r] = f2tf32(v.x); As[c4+1][r] = f2tf32(v.y);
                As[c4+2][r] = f2tf32(v.z); As[c4+3][r] = f2tf32(v.w);
            }
        }
        if (BT) {
            constexpr int CP  = BK/4;
            constexpr int RPP = NT / CP;
            #pragma unroll
            for (int p = 0; p < BN/RPP; p++) {
                int r  = tid / CP + p * RPP;
                int c4 = (tid % CP) * 4;
                const float4 v = *(const float4*)(Bm + (long)(n0 + r) * ldb + k0 + c4);
                Bs[c4+0][r] = f2tf32(v.x); Bs[c4+1][r] = f2tf32(v.y);
                Bs[c4+2][r] = f2tf32(v.z); Bs[c4+3][r] = f2tf32(v.w);
            }
        } else {
            constexpr int CP  = BN/4;
            constexpr int RPP = NT / CP;
            #pragma unroll
            for (int p = 0; p < BK/RPP; p++) {
                int r  = tid / CP + p * RPP;
                int c4 = (tid % CP) * 4;
                const float4 v = *(const float4*)(Bm + (long)(k0 + r) * ldb + n0 + c4);
                Bs[r][c4+0] = f2tf32(v.x); Bs[r][c4+1] = f2tf32(v.y);
                Bs[r][c4+2] = f2tf32(v.z); Bs[r][c4+3] = f2tf32(v.w);
            }
        }
        __syncthreads();

        #pragma unroll
        for (int kk = 0; kk < BK; kk += 8) {
            uint32_t af[MI][4], bf[NI][2];
            #pragma unroll
            for (int i = 0; i < MI; i++) {
                int mmx = wm*WTM + i*16;
                af[i][0] = As[kk+lc  ][mmx+lr  ];
                af[i][1] = As[kk+lc  ][mmx+lr+8];
                af[i][2] = As[kk+lc+4][mmx+lr  ];
                af[i][3] = As[kk+lc+4][mmx+lr+8];
            }
            #pragma unroll
            for (int j = 0; j < NI; j++) {
                int nn = wn*WTN + j*8;
                bf[j][0] = Bs[kk+lc  ][nn+lr];
                bf[j][1] = Bs[kk+lc+4][nn+lr];
            }
            #pragma unroll
            for (int i = 0; i < MI; i++)
                #pragma unroll
                for (int j = 0; j < NI; j++)
                    mma_tf32(acc[i][j], af[i], bf[j]);
        }
        __syncthreads();
    }

    #pragma unroll
    for (int i = 0; i < MI; i++) {
        #pragma unroll
        for (int j = 0; j < NI; j++) {
            const int  mmx = m0 + wm*WTM + i*16 + lr;
            const int  nn  = n0 + wn*WTN + j*8 + lc*2;
            float2 v0 = make_float2(acc[i][j][0]*alpha, acc[i][j][1]*alpha);
            float2 v1 = make_float2(acc[i][j][2]*alpha, acc[i][j][3]*alpha);
            if (bias) {
                const float2 bb = *(const float2*)(bias + nn);
                v0.x += bb.x; v0.y += bb.y;
                v1.x += bb.x; v1.y += bb.y;
            }
            *(float2*)(C + (long)mmx * ldc + nn)     = v0;
            *(float2*)(C + (long)(mmx+8) * ldc + nn) = v1;
        }
    }
}

// ---------------------------------------------------------------------------
// Fused flash attention with graph mask.
// One CTA = 128 q-rows of one (b,h). 8 warps, warp w owns rows 16w..16w+15.
// Streams 16 tiles of 64 keys. Scores never hit global memory.
// Smem strides chosen so all MMA fragment LDS are bank-conflict-free:
//   stride 68 == 4 (mod 32) -> bank = 4*lr + lc (distinct over 32 lanes)
//   stride 72 == 8 (mod 32) -> bank = 8*lc + lr (distinct over 32 lanes)
// ---------------------------------------------------------------------------
#define FL_SMEM ((128*68 + 64*68 + 64*72 + 128*68) * 4)

__global__ void __launch_bounds__(256, 2)
flash_kernel(const float* __restrict__ qkv, const unsigned* __restrict__ adj,
             float* __restrict__ attn_out)
{
    extern __shared__ uint32_t smf[];
    uint32_t (*Qs)[68] = (uint32_t(*)[68])(smf);                              // [qrow][hd]
    uint32_t (*Ks)[68] = (uint32_t(*)[68])(smf + 128*68);                     // [key][hd]
    uint32_t (*Vs)[72] = (uint32_t(*)[72])(smf + 128*68 + 64*68);             // [key][hd]
    uint32_t (*Ps)[68] = (uint32_t(*)[68])(smf + 128*68 + 64*68 + 64*72);     // [qrow][key]

    const int q0 = blockIdx.x * 128;
    const int b  = blockIdx.y / H_;
    const int h  = blockIdx.y % H_;

    const int tid  = threadIdx.x;
    const int wid  = tid >> 5;
    const int lane = tid & 31;
    const int lr   = lane >> 2;
    const int lc   = lane & 3;
    const int mm   = wid * 16;

    const float* qb = qkv + (long)b*L_*D3_ + h*HD_;
    const float* kb = qb + D_;
    const float* vb = qb + 2*D_;

    // ---- Q tile (pre-scaled by 1/sqrt(64) = 0.125)
    {
        const int r  = tid >> 4;          // 0..15
        const int c4 = (tid & 15) * 4;    // 0..60
        #pragma unroll
        for (int p = 0; p < 8; p++) {
            const float4 v = *(const float4*)(qb + (long)(q0 + r + p*16)*D3_ + c4);
            Qs[r+p*16][c4+0] = f2tf32(v.x * 0.125f);
            Qs[r+p*16][c4+1] = f2tf32(v.y * 0.125f);
            Qs[r+p*16][c4+2] = f2tf32(v.z * 0.125f);
            Qs[r+p*16][c4+3] = f2tf32(v.w * 0.125f);
        }
    }

    const int r0g = q0 + mm + lr;
    const int r1g = r0g + 8;
    const unsigned* adj0 = adj + (long)r0g * ADJW;
    const unsigned* adj1 = adj + (long)r1g * ADJW;

    float o[8][4];
    #pragma unroll
    for (int j = 0; j < 8; j++)
        #pragma unroll
        for (int r = 0; r < 4; r++) o[j][r] = 0.0f;
    float m0 = -INFINITY, m1 = -INFINITY, l0 = 0.0f, l1 = 0.0f;

    for (int kt = 0; kt < 16; kt++) {
        const int kbase = kt * 64;
        // ---- K/V tiles (coalesced float4, ~2-way STS conflicts max)
        {
            const int r  = tid >> 4;
            const int c4 = (tid & 15) * 4;
            #pragma unroll
            for (int p = 0; p < 4; p++) {
                const long row = (long)(kbase + r + p*16) * D3_;
                const float4 kv = *(const float4*)(kb + row + c4);
                Ks[r+p*16][c4+0] = f2tf32(kv.x); Ks[r+p*16][c4+1] = f2tf32(kv.y);
                Ks[r+p*16][c4+2] = f2tf32(kv.z); Ks[r+p*16][c4+3] = f2tf32(kv.w);
                const float4 vv = *(const float4*)(vb + row + c4);
                Vs[r+p*16][c4+0] = f2tf32(vv.x); Vs[r+p*16][c4+1] = f2tf32(vv.y);
                Vs[r+p*16][c4+2] = f2tf32(vv.z); Vs[r+p*16][c4+3] = f2tf32(vv.w);
            }
        }
        __syncthreads();

        // ---- S = (Q/8) K^T : warp tile 16 x 64
        float sc[8][4];
        #pragma unroll
        for (int j = 0; j < 8; j++)
            #pragma unroll
            for (int r = 0; r < 4; r++) sc[j][r] = 0.0f;

        #pragma unroll
        for (int kk = 0; kk < 64; kk += 8) {
            uint32_t af[4];
            af[0] = Qs[mm+lr  ][kk+lc  ];
            af[1] = Qs[mm+lr+8][kk+lc  ];
            af[2] = Qs[mm+lr  ][kk+lc+4];
            af[3] = Qs[mm+lr+8][kk+lc+4];
            #pragma unroll
            for (int j = 0; j < 8; j++) {
                uint32_t bf[2];
                bf[0] = Ks[8*j+lr][kk+lc  ];
                bf[1] = Ks[8*j+lr][kk+lc+4];
                mma_tf32(sc[j], af, bf);
            }
        }

        // ---- mask + online softmax (rows lr / lr+8 of warp tile)
        const unsigned wA0 = adj0[2*kt], wA1 = adj0[2*kt+1];
        const unsigned wB0 = adj1[2*kt], wB1 = adj1[2*kt+1];
        float tm0 = -INFINITY, tm1 = -INFINITY;
        unsigned mk = 0;
        #pragma unroll
        for (int j = 0; j < 8; j++) {
            const int cbit = (8*j + 2*lc) & 31;
            const unsigned wa = (j < 4) ? wA0 : wA1;
            const unsigned wb = (j < 4) ? wB0 : wB1;
            const unsigned f00 = (wa >> cbit) & 1u;
            const unsigned f01 = (wa >> (cbit+1)) & 1u;
            const unsigned f10 = (wb >> cbit) & 1u;
            const unsigned f11 = (wb >> (cbit+1)) & 1u;
            mk |= (f00 | (f01 << 1) | (f10 << 2) | (f11 << 3)) << (4*j);
            if (!f00) tm0 = fmaxf(tm0, sc[j][0]);
            if (!f01) tm0 = fmaxf(tm0, sc[j][1]);
            if (!f10) tm1 = fmaxf(tm1, sc[j][2]);
            if (!f11) tm1 = fmaxf(tm1, sc[j][3]);
        }
        tm0 = fmaxf(tm0, __shfl_xor_sync(0xFFFFFFFFu, tm0, 1));
        tm0 = fmaxf(tm0, __shfl_xor_sync(0xFFFFFFFFu, tm0, 2));
        tm1 = fmaxf(tm1, __shfl_xor_sync(0xFFFFFFFFu, tm1, 1));
        tm1 = fmaxf(tm1, __shfl_xor_sync(0xFFFFFFFFu, tm1, 2));

        const float mn0 = fmaxf(m0, tm0);
        const float mn1 = fmaxf(m1, tm1);
        const float a0 = (m0 == -INFINITY) ? 0.0f : __expf(m0 - mn0);
        const float a1 = (m1 == -INFINITY) ? 0.0f : __expf(m1 - mn1);
        m0 = mn0; m1 = mn1;

        float rs0 = 0.0f, rs1 = 0.0f;
        #pragma unroll
        for (int j = 0; j < 8; j++) {
            const unsigned mj = mk >> (4*j);
            const float p0 = (mj & 1u) ? 0.0f : __expf(sc[j][0] - mn0);
            const float p1 = (mj & 2u) ? 0.0f : __expf(sc[j][1] - mn0);
            const float p2 = (mj & 4u) ? 0.0f : __expf(sc[j][2] - mn1);
            const float p3 = (mj & 8u) ? 0.0f : __expf(sc[j][3] - mn1);
            rs0 += p0 + p1;
            rs1 += p2 + p3;
            Ps[mm+lr  ][8*j+2*lc  ] = f2tf32(p0);
            Ps[mm+lr  ][8*j+2*lc+1] = f2tf32(p1);
            Ps[mm+lr+8][8*j+2*lc  ] = f2tf32(p2);
            Ps[mm+lr+8][8*j+2*lc+1] = f2tf32(p3);
        }
        rs0 += __shfl_xor_sync(0xFFFFFFFFu, rs0, 1);
        rs0 += __shfl_xor_sync(0xFFFFFFFFu, rs0, 2);
        rs1 += __shfl_xor_sync(0xFFFFFFFFu, rs1, 1);
        rs1 += __shfl_xor_sync(0xFFFFFFFFu, rs1, 2);
        l0 = a0*l0 + rs0;
        l1 = a1*l1 + rs1;

        #pragma unroll
        for (int j = 0; j < 8; j++) {
            o[j][0] *= a0; o[j][1] *= a0;
            o[j][2] *= a1; o[j][3] *= a1;
        }

        __syncwarp();   // P rows are warp-private: STS -> LDS visibility

        // ---- O += P V : m16 n64 k64
        #pragma unroll
        for (int kk = 0; kk < 64; kk += 8) {
            uint32_t af[4];
            af[0] = Ps[mm+lr  ][kk+lc  ];
            af[1] = Ps[mm+lr+8][kk+lc  ];
            af[2] = Ps[mm+lr  ][kk+lc+4];
            af[3] = Ps[mm+lr+8][kk+lc+4];
            #pragma unroll
            for (int j = 0; j < 8; j++) {
                uint32_t bf[2];
                bf[0] = Vs[kk+lc  ][8*j+lr];
                bf[1] = Vs[kk+lc+4][8*j+lr];
                mma_tf32(o[j], af, bf);
            }
        }
        __syncthreads();   // before next K/V overwrite
    }

    // ---- epilogue: O / l -> attn_out[b, q, h*64 + n]
    const float i0 = 1.0f / l0;
    const float i1 = 1.0f / l1;
    float* ob = attn_out + (long)b*L_*D_ + h*HD_;
    #pragma unroll
    for (int j = 0; j < 8; j++) {
        const int nn = 8*j + 2*lc;
        *(float2*)(ob + (long)r0g*D_ + nn) = make_float2(o[j][0]*i0, o[j][1]*i0);
        *(float2*)(ob + (long)r1g*D_ + nn) = make_float2(o[j][2]*i1, o[j][3]*i1);
    }
}

// ---------------------------------------------------------------------------
// Launch
// ---------------------------------------------------------------------------
extern "C" void kernel_launch(void* const* d_in, const int* in_sizes, int n_in,
                              void* d_out, int out_size)
{
    const float* x     = (const float*)d_in[0];
    const int*   edges = (const int*)  d_in[1];
    const float* w_qkv = (const float*)d_in[2];
    const float* b_qkv = (const float*)d_in[3];
    const float* w_out = (const float*)d_in[4];
    const float* b_out = (const float*)d_in[5];
    float* out = (float*)d_out;
    const int E = in_sizes[1] / 2;

    float *qkv, *attn; unsigned* adj;
    cudaGetSymbolAddress((void**)&qkv,  g_qkv);
    cudaGetSymbolAddress((void**)&attn, g_attn);
    cudaGetSymbolAddress((void**)&adj,  g_adj);

    static int smem_set = 0;
    if (!smem_set) {
        cudaFuncSetAttribute(flash_kernel,
                             cudaFuncAttributeMaxDynamicSharedMemorySize, FL_SMEM);
        smem_set = 1;
    }

    // 1) adjacency bitmask
    zero_adj_kernel<<<(L_*ADJW + 255) / 256, 256>>>(adj);
    build_adj_kernel<<<(E + 255) / 256, 256>>>(adj, edges, E);

    // 2) QKV projection: [4096,3072] = X[4096,1024] @ Wqkv[3072,1024]^T + b
    {
        dim3 g(D3_/128, (B_*L_)/128, 1);
        gemm_tc<128,128,16,2,4,true><<<g, 256>>>(
            x, w_qkv, b_qkv, qkv,
            D_, D_, D3_, D_,
            1, 0,0, 0,0, 0,0, 1.0f);
    }

    // 3) fused masked attention (scores never materialized)
    {
        dim3 g(L_/128, B_*H_);
        flash_kernel<<<g, 256, FL_SMEM>>>(qkv, adj, attn);
    }

    // 4) out projection: [4096,1024] = attn[4096,1024] @ Wout[1024,1024]^T + b
    {
        dim3 g(D_/128, (B_*L_)/128, 1);
        gemm_tc<128,128,16,2,4,true><<<g, 256>>>(
            attn, w_out, b_out, out,
            D_, D_, D_, D_,
            1, 0,0, 0,0, 0,0, 1.0f);
    }
}